// round 14
// baseline (speedup 1.0000x reference)
#include <cuda_runtime.h>
#include <math.h>

// Problem constants
#define BATCH 4
#define SEQ   2048
#define DIMC  1024
#define NHEAD 16
#define HDIM  64
#define MROWS (BATCH * SEQ)      // 8192
#define QK_SCALE 0.125f          // 64^-0.5

// Scratch (device globals — allocation-free per harness rules)
__device__ float g_q[(size_t)BATCH * NHEAD * SEQ * HDIM];
__device__ float g_k[(size_t)BATCH * NHEAD * SEQ * HDIM];
__device__ float g_v[(size_t)BATCH * NHEAD * SEQ * HDIM];
__device__ float g_attn[(size_t)MROWS * DIMC];

// ---------------- packed f32x2 helpers (sm_100+ PTX, plain target) ----------
typedef unsigned long long u64;
__device__ __forceinline__ void fma2(u64& d, u64 a, u64 b) {
    asm("fma.rn.f32x2 %0, %1, %2, %0;" : "+l"(d) : "l"(a), "l"(b));
}
__device__ __forceinline__ void mul2(u64& d, u64 a) {
    asm("mul.rn.f32x2 %0, %0, %1;" : "+l"(d) : "l"(a));
}
__device__ __forceinline__ u64 pack2(float x, float y) {
    u64 r;
    asm("mov.b64 %0, {%1, %2};" : "=l"(r) : "f"(x), "f"(y));
    return r;
}
__device__ __forceinline__ float2 unpack2(u64 v) {
    float2 r;
    asm("mov.b64 {%0, %1}, %2;" : "=f"(r.x), "=f"(r.y) : "l"(v));
    return r;
}

// ---------------------------------------------------------------------------
// Tiled SGEMM (unchanged from R12): C[M,N] = A[M,K] @ B[K,N] + bias[N]
// 128x128 tile, K-tile 16, 256 threads, 8x8 microtile, FFMA2 inner product.
// MODE 0: epilogue scatters into g_q/g_k/g_v. MODE 1: A = g_attn, plain store.
// ---------------------------------------------------------------------------
template <int MODE>
__global__ __launch_bounds__(256) void sgemm_k(
    const float* __restrict__ A, const float* __restrict__ B,
    const float* __restrict__ bias, float* __restrict__ C,
    int K, int Ncols)
{
    __shared__ float As[16][132];   // [k][m] transposed, padded
    __shared__ float Bs[16][132];   // [k][n], padded

    const float* __restrict__ Ap = (MODE == 0) ? A : g_attn;

    const int tid = threadIdx.x;
    const int m0 = blockIdx.y * 128;
    const int n0 = blockIdx.x * 128;
    const int ty = tid >> 4;       // 0..15 -> 8 rows each
    const int tx = tid & 15;       // 0..15 -> cols tx*4 and 64+tx*4

    u64 acc2[8][4] = {};

    for (int k0 = 0; k0 < K; k0 += 16) {
#pragma unroll
        for (int i = 0; i < 2; i++) {
            const int idx  = tid * 2 + i;          // 0..511
            const int arow = idx >> 2;
            const int aseg = idx & 3;
            float4 av = *(const float4*)(Ap + (size_t)(m0 + arow) * K + k0 + aseg * 4);
            As[aseg * 4 + 0][arow] = av.x;
            As[aseg * 4 + 1][arow] = av.y;
            As[aseg * 4 + 2][arow] = av.z;
            As[aseg * 4 + 3][arow] = av.w;
        }
#pragma unroll
        for (int i = 0; i < 2; i++) {
            const int idx  = tid * 2 + i;
            const int brow = idx >> 5;
            const int bc4  = idx & 31;
            float4 bv = *(const float4*)(B + (size_t)(k0 + brow) * Ncols + n0 + bc4 * 4);
            *(float4*)&Bs[brow][bc4 * 4] = bv;
        }
        __syncthreads();

#pragma unroll
        for (int kk = 0; kk < 16; kk++) {
            float4 a0 = *(const float4*)&As[kk][ty * 8];
            float4 a1 = *(const float4*)&As[kk][ty * 8 + 4];
            float4 b0 = *(const float4*)&Bs[kk][tx * 4];
            float4 b1 = *(const float4*)&Bs[kk][64 + tx * 4];
            u64 bp[4] = {pack2(b0.x, b0.y), pack2(b0.z, b0.w),
                         pack2(b1.x, b1.y), pack2(b1.z, b1.w)};
            float ar[8] = {a0.x, a0.y, a0.z, a0.w, a1.x, a1.y, a1.z, a1.w};
#pragma unroll
            for (int i = 0; i < 8; i++) {
                u64 ad = pack2(ar[i], ar[i]);
#pragma unroll
                for (int j = 0; j < 4; j++)
                    fma2(acc2[i][j], ad, bp[j]);
            }
        }
        __syncthreads();
    }

    const int nbs[2] = {n0 + tx * 4, n0 + 64 + tx * 4};
    float4 bia[2] = {*(const float4*)(bias + nbs[0]),
                     *(const float4*)(bias + nbs[1])};
#pragma unroll
    for (int i = 0; i < 8; i++) {
        const int m = m0 + ty * 8 + i;
#pragma unroll
        for (int g = 0; g < 2; g++) {
            float2 c0 = unpack2(acc2[i][g * 2 + 0]);
            float2 c1 = unpack2(acc2[i][g * 2 + 1]);
            float4 v = {c0.x + bia[g].x, c0.y + bia[g].y,
                        c1.x + bia[g].z, c1.y + bia[g].w};
            const int nb = nbs[g];
            if (MODE == 0) {
                const int which = nb >> 10;
                const int h     = (nb & 1023) >> 6;
                const int d     = nb & 63;
                const int b     = m >> 11;
                const int s     = m & 2047;
                float* dst = (which == 0) ? g_q : (which == 1) ? g_k : g_v;
                *(float4*)(dst + (((size_t)(b * NHEAD + h)) * SEQ + s) * HDIM + d) = v;
            } else {
                *(float4*)(C + (size_t)m * Ncols + nb) = v;
            }
        }
    }
}

// ---------------------------------------------------------------------------
// Flash attention, zero-pack FFMA2 inner loops.
// 256 threads = 16(ty: 4 q-rows) x 16(tx). Q tile 64, K/V tile 32.
// S-phase: pairs along d — Q and K natural row-major, ulonglong2 loads;
//          thread's S cols = {tx, tx+16}; horizontal add at end.
// Softmax: writes P pre-duplicated (p,p) u64 into sPd (stride 34 u64).
// PV: pd = ulonglong2 (2 dup-pairs per load), V natural pairs along d.
// sPd overlays sK (dead after S-phase); extra syncthreads guards overwrite.
// ---------------------------------------------------------------------------
__global__ __launch_bounds__(256) void attn_k()
{
    __shared__ __align__(16) float sQ[64 * 68];        // natural [row][d], 17408 B
    __shared__ __align__(16) float sV[32 * 68];        // natural [k][d],    8704 B
    __shared__ __align__(16) u64   sOvl[64 * 34];      // sPd / sK overlay, 17408 B
    float* sK = (float*)sOvl;                          // [k][d] stride 68 (8704 B)

    const int tid = threadIdx.x;
    const int bh  = blockIdx.y;              // 0..63
    const int q0  = blockIdx.x * 64;
    const int ty  = tid >> 4;                // 0..15 -> 4 q-rows
    const int tx  = tid & 15;                // S cols {tx, tx+16}; O cols tx*4..+3

    const float* __restrict__ Qp = g_q + (size_t)bh * SEQ * HDIM;
    const float* __restrict__ Kp = g_k + (size_t)bh * SEQ * HDIM;
    const float* __restrict__ Vp = g_v + (size_t)bh * SEQ * HDIM;

    // Load + scale Q tile (64x64), natural layout
#pragma unroll
    for (int i = 0; i < 4; i++) {
        const int idx = tid * 4 + i;         // 0..1023
        const int r = idx >> 4;
        const int d = (idx & 15) * 4;
        float4 qv = *(const float4*)(Qp + (size_t)(q0 + r) * HDIM + d);
        qv.x *= QK_SCALE; qv.y *= QK_SCALE; qv.z *= QK_SCALE; qv.w *= QK_SCALE;
        *(float4*)&sQ[r * 68 + d] = qv;
    }

    u64 o2[4][2] = {};                       // 4 rows x 2 d-pairs (cols tx*4..+3)
    float mrow[4] = {-1e30f, -1e30f, -1e30f, -1e30f};
    float lrow[4] = {0.f, 0.f, 0.f, 0.f};

    for (int kt = 0; kt < SEQ / 32; kt++) {
        __syncthreads();   // prior tile's PV reads of sV/sPd done (also Q init)
        // Load K (into overlay) and V, natural [r][d]
#pragma unroll
        for (int i = 0; i < 2; i++) {
            const int idx = tid * 2 + i;     // 0..511
            const int r = idx >> 4;
            const int d = (idx & 15) * 4;
            *(float4*)&sK[r * 68 + d] = *(const float4*)(Kp + (size_t)(kt * 32 + r) * HDIM + d);
            *(float4*)&sV[r * 68 + d] = *(const float4*)(Vp + (size_t)(kt * 32 + r) * HDIM + d);
        }
        __syncthreads();

        // S-phase: pairs along d, zero packs. s2[i][j]: (even-d, odd-d) partials
        u64 s2[4][2] = {};
#pragma unroll 8
        for (int d4 = 0; d4 < HDIM; d4 += 4) {
            ulonglong2 k0 = *(const ulonglong2*)&sK[tx * 68 + d4];
            ulonglong2 k1 = *(const ulonglong2*)&sK[(tx + 16) * 68 + d4];
#pragma unroll
            for (int i = 0; i < 4; i++) {
                ulonglong2 q = *(const ulonglong2*)&sQ[(ty * 4 + i) * 68 + d4];
                fma2(s2[i][0], q.x, k0.x);
                fma2(s2[i][0], q.y, k0.y);
                fma2(s2[i][1], q.x, k1.x);
                fma2(s2[i][1], q.y, k1.y);
            }
        }
        float s[4][2];
#pragma unroll
        for (int i = 0; i < 4; i++) {
#pragma unroll
            for (int j = 0; j < 2; j++) {
                float2 h = unpack2(s2[i][j]);
                s[i][j] = h.x + h.y;
            }
        }

        __syncthreads();   // ALL warps done reading sK before sPd overwrites it

        // Online softmax per q-row; write P duplicated into sPd
        float corr[4];
#pragma unroll
        for (int i = 0; i < 4; i++) {
            float tmax = fmaxf(s[i][0], s[i][1]);
            tmax = fmaxf(tmax, __shfl_xor_sync(0xffffffffu, tmax, 1));
            tmax = fmaxf(tmax, __shfl_xor_sync(0xffffffffu, tmax, 2));
            tmax = fmaxf(tmax, __shfl_xor_sync(0xffffffffu, tmax, 4));
            tmax = fmaxf(tmax, __shfl_xor_sync(0xffffffffu, tmax, 8));
            const float newm = fmaxf(mrow[i], tmax);
            corr[i] = __expf(mrow[i] - newm);
            const float p0 = __expf(s[i][0] - newm);   // col tx
            const float p1 = __expf(s[i][1] - newm);   // col tx+16
            sOvl[(ty * 4 + i) * 34 + tx]      = pack2(p0, p0);
            sOvl[(ty * 4 + i) * 34 + tx + 16] = pack2(p1, p1);
            float ts = p0 + p1;
            ts += __shfl_xor_sync(0xffffffffu, ts, 1);
            ts += __shfl_xor_sync(0xffffffffu, ts, 2);
            ts += __shfl_xor_sync(0xffffffffu, ts, 4);
            ts += __shfl_xor_sync(0xffffffffu, ts, 8);
            lrow[i] = lrow[i] * corr[i] + ts;
            mrow[i] = newm;
        }
#pragma unroll
        for (int i = 0; i < 4; i++) {
            u64 cd = pack2(corr[i], corr[i]);
            mul2(o2[i][0], cd);
            mul2(o2[i][1], cd);
        }

        __syncwarp();   // sPd rows of this ty group are warp-local

        // PV: zero packs. Per k2: 2 kk via ulonglong2 pd (dup pairs) + natural V
#pragma unroll 4
        for (int k2 = 0; k2 < 16; k2++) {
            ulonglong2 v0 = *(const ulonglong2*)&sV[(2 * k2 + 0) * 68 + tx * 4];
            ulonglong2 v1 = *(const ulonglong2*)&sV[(2 * k2 + 1) * 68 + tx * 4];
#pragma unroll
            for (int i = 0; i < 4; i++) {
                ulonglong2 pd = *(const ulonglong2*)&sOvl[(ty * 4 + i) * 34 + 2 * k2];
                fma2(o2[i][0], pd.x, v0.x);
                fma2(o2[i][1], pd.x, v0.y);
                fma2(o2[i][0], pd.y, v1.x);
                fma2(o2[i][1], pd.y, v1.y);
            }
        }
    }

    // Epilogue: normalize and store to [b][s][h*64+d]
    const int b = bh >> 4;
    const int h = bh & 15;
#pragma unroll
    for (int i = 0; i < 4; i++) {
        const float inv = 1.0f / lrow[i];
        float2 c0 = unpack2(o2[i][0]);
        float2 c1 = unpack2(o2[i][1]);
        float4 ov = {c0.x * inv, c0.y * inv, c1.x * inv, c1.y * inv};
        float* op = g_attn + ((size_t)(b * SEQ + q0 + ty * 4 + i)) * DIMC
                  + h * HDIM + tx * 4;
        *(float4*)op = ov;
    }
}

// ---------------------------------------------------------------------------
extern "C" void kernel_launch(void* const* d_in, const int* in_sizes, int n_in,
                              void* d_out, int out_size)
{
    const float* x      = (const float*)d_in[0];
    const float* w_qkv  = (const float*)d_in[1];
    const float* b_qkv  = (const float*)d_in[2];
    const float* w_proj = (const float*)d_in[3];
    const float* b_proj = (const float*)d_in[4];
    float* out = (float*)d_out;

    // 1) qkv = x @ w_qkv + b_qkv, scattered into g_q/g_k/g_v [bh][s][d]
    {
        dim3 grid(3 * DIMC / 128, MROWS / 128);   // (24, 64)
        sgemm_k<0><<<grid, 256>>>(x, w_qkv, b_qkv, nullptr, DIMC, 3 * DIMC);
    }
    // 2) attention -> g_attn [b][s][h*64+d]
    {
        dim3 grid(SEQ / 64, BATCH * NHEAD);       // (32, 64)
        attn_k<<<grid, 256>>>();
    }
    // 3) out = g_attn @ w_proj + b_proj
    {
        dim3 grid(DIMC / 128, MROWS / 128);       // (8, 64)
        sgemm_k<1><<<grid, 256>>>(nullptr, w_proj, b_proj, out, DIMC, DIMC);
    }
}